// round 13
// baseline (speedup 1.0000x reference)
#include <cuda_runtime.h>
#include <cstdint>

constexpr int Bc = 32;
constexpr int Hc = 512;
constexpr int Wc = 512;
constexpr int Pc = 100000;
constexpr long long Nc = (long long)Bc * Pc;   // 3,200,000 points
constexpr int BDIM   = 256;
constexpr int PPT    = 4;                      // points per chunk
constexpr int GRID   = 148 * 5;                // persistent, one wave at 5 CTAs/SM (regs=48)
constexpr int NCHUNK = (int)(Nc / PPT);        // 800,000 chunks
static_assert(Nc % PPT == 0, "chunks tile exactly");
static_assert(Pc % PPT == 0, "4 consecutive points always share a batch index");

__device__ float g_zero = 0.0f;   // source for the zero-init memcpy node

__device__ __forceinline__ float point_loss(float zA, float zB, int o) {
    float d  = zA - zB;
    float gt = (float)o - 1.0f;          // in {-1, 0, +1}
    float sm = log1pf(expf(-gt * d));    // soft-margin branch (gt = +/-1)
    return (o == 1) ? (d * d) : sm;
}

__device__ __forceinline__ int4 ldcs4(const int* p) {
    return __ldcs(reinterpret_cast<const int4*>(p));
}

struct Chunk { int4 xa, ya, xb, yb, o4; };

__device__ __forceinline__ Chunk load_chunk(const int* xA, const int* yA,
                                            const int* xB, const int* yB,
                                            const int* ord, long long base) {
    Chunk c;
    c.xa = ldcs4(xA + base);
    c.ya = ldcs4(yA + base);
    c.xb = ldcs4(xB + base);
    c.yb = ldcs4(yB + base);
    c.o4 = ldcs4(ord + base);
    return c;
}

__global__ __launch_bounds__(BDIM)
void loss_kernel(const float* __restrict__ img,
                 const int* __restrict__ xA,
                 const int* __restrict__ yA,
                 const int* __restrict__ xB,
                 const int* __restrict__ yB,
                 const int* __restrict__ ord,
                 float* __restrict__ out)
{
    const int gtid   = blockIdx.x * BDIM + threadIdx.x;
    const int stride = GRID * BDIM;

    float acc = 0.0f;

    int c = gtid;
    Chunk cur;
    if (c < NCHUNK)
        cur = load_chunk(xA, yA, xB, yB, ord, (long long)c * PPT);

    while (c < NCHUNK) {
        const long long base = (long long)c * PPT;
        const int b = (int)(base / Pc);
        const float* __restrict__ imgb = img + (long long)b * (Hc * Wc);

        // Offsets: y*512 + x
        unsigned offA0 = ((unsigned)cur.ya.x << 9) | (unsigned)cur.xa.x;
        unsigned offA1 = ((unsigned)cur.ya.y << 9) | (unsigned)cur.xa.y;
        unsigned offA2 = ((unsigned)cur.ya.z << 9) | (unsigned)cur.xa.z;
        unsigned offA3 = ((unsigned)cur.ya.w << 9) | (unsigned)cur.xa.w;
        unsigned offB0 = ((unsigned)cur.yb.x << 9) | (unsigned)cur.xb.x;
        unsigned offB1 = ((unsigned)cur.yb.y << 9) | (unsigned)cur.xb.y;
        unsigned offB2 = ((unsigned)cur.yb.z << 9) | (unsigned)cur.xb.z;
        unsigned offB3 = ((unsigned)cur.yb.w << 9) | (unsigned)cur.xb.w;
        int4 o4 = cur.o4;

        // Issue all 8 gathers (current chunk)
        float zA0 = __ldg(imgb + offA0);
        float zA1 = __ldg(imgb + offA1);
        float zA2 = __ldg(imgb + offA2);
        float zA3 = __ldg(imgb + offA3);
        float zB0 = __ldg(imgb + offB0);
        float zB1 = __ldg(imgb + offB1);
        float zB2 = __ldg(imgb + offB2);
        float zB3 = __ldg(imgb + offB3);

        // Prefetch next chunk's indices — overlaps with the gathers above
        const int cn = c + stride;
        if (cn < NCHUNK)
            cur = load_chunk(xA, yA, xB, yB, ord, (long long)cn * PPT);

        acc += point_loss(zA0, zB0, o4.x)
             + point_loss(zA1, zB1, o4.y)
             + point_loss(zA2, zB2, o4.z)
             + point_loss(zA3, zB3, o4.w);

        c = cn;
    }

    // Warp reduce
    #pragma unroll
    for (int off = 16; off > 0; off >>= 1)
        acc += __shfl_xor_sync(0xFFFFFFFFu, acc, off);

    __shared__ float warp_sums[BDIM / 32];
    int lane = threadIdx.x & 31;
    int wid  = threadIdx.x >> 5;
    if (lane == 0) warp_sums[wid] = acc;
    __syncthreads();

    if (threadIdx.x == 0) {
        float v = warp_sums[0];
        #pragma unroll
        for (int w = 1; w < BDIM / 32; w++) v += warp_sums[w];
        // Pre-scaled fire-and-forget reduction straight into the output.
        atomicAdd(out, v * (1.0f / (float)Nc));
    }
}

extern "C" void kernel_launch(void* const* d_in, const int* in_sizes, int n_in,
                              void* d_out, int out_size)
{
    const float* img = (const float*)d_in[0];
    const int*   xA  = (const int*)d_in[1];
    const int*   yA  = (const int*)d_in[2];
    const int*   xB  = (const int*)d_in[3];
    const int*   yB  = (const int*)d_in[4];
    const int*   ord = (const int*)d_in[5];
    float* out = (float*)d_out;

    // Zero-init the (poisoned) output via a cheap D2D memcpy node.
    void* zero_addr = nullptr;
    cudaGetSymbolAddress(&zero_addr, g_zero);
    cudaMemcpyAsync(out, zero_addr, sizeof(float), cudaMemcpyDeviceToDevice, 0);

    loss_kernel<<<GRID, BDIM>>>(img, xA, yA, xB, yB, ord, out);
}